// round 13
// baseline (speedup 1.0000x reference)
#include <cuda_runtime.h>
#include <cuda_fp16.h>
#include <math.h>
#include <stdint.h>
#include <float.h>

// ---------------- Scratch (device globals; no allocation allowed) ----------------
__device__ float g_ps[25600 * 196];     // ps_map
__device__ float g_bb[25600 * 196];     // bb_map
__device__ float g_roisall[600 * 5];
__device__ float g_scores[600];
__device__ uint4 g_Bsp[100352];         // 1.6 MB pre-split W (frag order)

#define A_SCALE 64.0f
#define B_SCALE 1024.0f
#define INV_SCALE (1.0f / 65536.0f)

// ================= helpers =================
__device__ __forceinline__ uint32_t smem_u32(const void* p) {
    uint32_t a;
    asm("{ .reg .u64 t; cvta.to.shared.u64 t, %1; cvt.u32.u64 %0, t; }" : "=r"(a) : "l"(p));
    return a;
}
__device__ __forceinline__ void cpa16(uint32_t saddr, const void* gptr) {
    asm volatile("cp.async.cg.shared.global [%0], [%1], 16;" :: "r"(saddr), "l"(gptr));
}
#define CP_COMMIT() asm volatile("cp.async.commit_group;" ::: "memory")
#define CP_WAIT1()  asm volatile("cp.async.wait_group 1;" ::: "memory")
#define CP_WAIT0()  asm volatile("cp.async.wait_group 0;" ::: "memory")

__device__ __forceinline__ void splith(float x, __half& h, __half& l) {
    h = __float2half_rn(x);
    l = __float2half_rn(x - __half2float(h));
}
__device__ __forceinline__ uint32_t packh2(__half a, __half b) {
    __half2 v = __halves2half2(a, b);
    return *reinterpret_cast<uint32_t*>(&v);
}
// packed split: same per-element rn rounding as splith/packh2, fewer instructions.
// result lo-half <- u.x path, hi-half <- u.y path (matches packh2(hx, hy)).
__device__ __forceinline__ void split2(float2 u, uint32_t& hi, uint32_t& lo) {
    float sx = u.x * A_SCALE;
    float sy = u.y * A_SCALE;
    uint32_t h;
    asm("cvt.rn.f16x2.f32 %0, %1, %2;" : "=r"(h) : "f"(sy), "f"(sx));
    __half2 hh = *reinterpret_cast<const __half2*>(&h);
    float2 hf = __half22float2(hh);
    float rx = sx - hf.x;
    float ry = sy - hf.y;
    uint32_t l;
    asm("cvt.rn.f16x2.f32 %0, %1, %2;" : "=r"(l) : "f"(ry), "f"(rx));
    hi = h;
    lo = l;
}

// f32-accumulator mma (dominant hi*hi pass)
__device__ __forceinline__ void mma_f16(float c[4], const uint32_t a[4],
                                        uint32_t b0, uint32_t b1) {
    asm volatile(
        "mma.sync.aligned.m16n8k16.row.col.f32.f16.f16.f32 "
        "{%0,%1,%2,%3}, {%4,%5,%6,%7}, {%8,%9}, {%0,%1,%2,%3};"
        : "+f"(c[0]), "+f"(c[1]), "+f"(c[2]), "+f"(c[3])
        : "r"(a[0]), "r"(a[1]), "r"(a[2]), "r"(a[3]), "r"(b0), "r"(b1));
}
// f16-accumulator mma (small correction passes)
__device__ __forceinline__ void mma_f16acc(uint32_t c[2], const uint32_t a[4],
                                           uint32_t b0, uint32_t b1) {
    asm volatile(
        "mma.sync.aligned.m16n8k16.row.col.f16.f16.f16.f16 "
        "{%0,%1}, {%2,%3,%4,%5}, {%6,%7}, {%0,%1};"
        : "+r"(c[0]), "+r"(c[1])
        : "r"(a[0]), "r"(a[1]), "r"(a[2]), "r"(a[3]), "r"(b0), "r"(b1));
}

// ================= prep_B: W -> fp16 hi/lo frag order ================
__global__ __launch_bounds__(256) void prep_B(const float* __restrict__ Wps,
                                              const float* __restrict__ Wbb,
                                              uint4* __restrict__ Bsp)
{
    int i = blockIdx.x * 256 + threadIdx.x;          // 0 .. 100,351
    if (i >= 100352) return;
    int ntc, nbase, base;
    if (i < 51200) { ntc = 25; nbase = 0; base = 0; }
    else           { ntc = 24; nbase = 200; base = 51200; }
    int li = i - base;
    int lane = li & 31;
    int j = li >> 5;
    int nt = j % ntc; j /= ntc;
    int ks = j & 1;
    int kt = j >> 1;
    int g = lane >> 2, t = lane & 3;
    int n = nbase + nt * 8 + g;
    int k = kt * 32 + ks * 16 + 2 * t;

    const float* W = (n < 196) ? Wps : Wbb;
    int nn = (n < 196) ? n : n - 196;
    float w0 = W[(size_t)k * 196 + nn] * B_SCALE;
    float w1 = W[(size_t)(k + 1) * 196 + nn] * B_SCALE;
    float w2 = W[(size_t)(k + 8) * 196 + nn] * B_SCALE;
    float w3 = W[(size_t)(k + 9) * 196 + nn] * B_SCALE;

    __half h0, l0, h1, l1, h2, l2, h3, l3;
    splith(w0, h0, l0); splith(w1, h1, l1);
    splith(w2, h2, l2); splith(w3, h3, l3);
    Bsp[i] = make_uint4(packh2(h0, h1), packh2(h2, h3),
                        packh2(l0, l1), packh2(l2, l3));
}

// ================= GEMM: fp16x3 mma, fp32 A via cp.async, split at consumption ====
#define ASTRIDE 36
#define ABUF (128 * ASTRIDE * 4)           // 18432 B per A stage
#define BBUF 25600
#define GEMM_SMEM (3 * ABUF + 3 * BBUF)    // 132096

template<int NTC, int NBASE, int BOFF>
__device__ __forceinline__ void gemm_body(
    const float* __restrict__ A, const uint4* __restrict__ Bsp,
    const float* __restrict__ bps, const float* __restrict__ bbb,
    float* __restrict__ Cps, float* __restrict__ Cbb, char* smem, int mt)
{
    const int tid = threadIdx.x;
    const int lane = tid & 31;
    const int wid = tid >> 5;
    const int g = lane >> 2;
    const int t = lane & 3;
    const uint32_t sbase = smem_u32(smem);

    float chh[NTC][4];
    uint32_t ccr[NTC][2];
#pragma unroll
    for (int nt = 0; nt < NTC; nt++) {
#pragma unroll
        for (int j = 0; j < 4; j++) chh[nt][j] = 0.0f;
        ccr[nt][0] = 0u;
        ccr[nt][1] = 0u;
    }

    const float* Abase = A + (size_t)mt * 128 * 1024;

    auto copy_stage = [&](int s, int buf) {
        uint32_t sa = sbase + buf * ABUF;
        const float* ga = Abase + s * 32;
#pragma unroll
        for (int i = 0; i < 4; i++) {
            int c = tid + i * 256;          // 0..1023
            int row = c >> 3, q = c & 7;
            cpa16(sa + row * (ASTRIDE * 4) + q * 16,
                  ga + (size_t)row * 1024 + q * 4);
        }
        const uint4* gb = Bsp + BOFF + (size_t)s * (NTC * 64);
        uint32_t sB = sbase + 3 * ABUF + buf * BBUF;
#pragma unroll
        for (int i = 0; i < 6; i++) {
            int o = tid + i * 256;
            cpa16(sB + o * 16, gb + o);
        }
        if (NTC == 25 && tid < 64) {
            int o = tid + 1536;
            cpa16(sB + o * 16, gb + o);
        }
        CP_COMMIT();
    };

    copy_stage(0, 0);
    copy_stage(1, 1);

    const int r0 = wid * 16 + g;

    for (int s = 0; s < 32; ++s) {
        if (s < 31) CP_WAIT1(); else CP_WAIT0();
        __syncthreads();
        if (s + 2 < 32) copy_stage(s + 2, (s + 2) % 3);

        const int buf = s % 3;
        const float* Af = reinterpret_cast<const float*>(smem + buf * ABUF);
        const uint4* Bs = reinterpret_cast<const uint4*>(smem + 3 * ABUF + buf * BBUF);

#pragma unroll
        for (int ks = 0; ks < 2; ks++) {
            const int k0 = ks * 16 + 2 * t;
            float2 u0 = *reinterpret_cast<const float2*>(&Af[r0 * ASTRIDE + k0]);
            float2 u1 = *reinterpret_cast<const float2*>(&Af[r0 * ASTRIDE + k0 + 8]);
            float2 u2 = *reinterpret_cast<const float2*>(&Af[(r0 + 8) * ASTRIDE + k0]);
            float2 u3 = *reinterpret_cast<const float2*>(&Af[(r0 + 8) * ASTRIDE + k0 + 8]);
            uint32_t ah[4], al[4];
            split2(u0, ah[0], al[0]);   // (g,   k0|k0+1)
            split2(u2, ah[1], al[1]);   // (g+8, k0|k0+1)
            split2(u1, ah[2], al[2]);   // (g,   k0+8|k0+9)
            split2(u3, ah[3], al[3]);   // (g+8, k0+8|k0+9)
#pragma unroll
            for (int nt = 0; nt < NTC; nt++) {
                uint4 q = Bs[(ks * NTC + nt) * 32 + lane];
                mma_f16acc(ccr[nt], al, q.x, q.y);   // lo_a * hi_b (f16 acc)
                mma_f16acc(ccr[nt], ah, q.z, q.w);   // hi_a * lo_b (f16 acc)
                mma_f16(chh[nt], ah, q.x, q.y);      // hi_a * hi_b (f32 acc)
            }
        }
    }

    const int rg = mt * 128 + r0;
#pragma unroll
    for (int nt = 0; nt < NTC; nt++) {
        int gc = NBASE + nt * 8 + t * 2;
        float bias0, bias1;
        float* Cout;
        int cc;
        if (gc < 196) { bias0 = bps[gc]; bias1 = bps[gc + 1]; Cout = Cps; cc = gc; }
        else { bias0 = bbb[gc - 196]; bias1 = bbb[gc - 195]; Cout = Cbb; cc = gc - 196; }
        __half2 q01 = *reinterpret_cast<__half2*>(&ccr[nt][0]);
        __half2 q23 = *reinterpret_cast<__half2*>(&ccr[nt][1]);
        float2 cr01 = __half22float2(q01);
        float2 cr23 = __half22float2(q23);
        float2 w0 = make_float2((chh[nt][0] + cr01.x) * INV_SCALE + bias0,
                                (chh[nt][1] + cr01.y) * INV_SCALE + bias1);
        float2 w1 = make_float2((chh[nt][2] + cr23.x) * INV_SCALE + bias0,
                                (chh[nt][3] + cr23.y) * INV_SCALE + bias1);
        *reinterpret_cast<float2*>(&Cout[(size_t)rg * 196 + cc]) = w0;
        *reinterpret_cast<float2*>(&Cout[(size_t)(rg + 8) * 196 + cc]) = w1;
    }
}

__global__ __launch_bounds__(256, 1) void gemm_mma(
    const float* __restrict__ A, const uint4* __restrict__ Bsp,
    const float* __restrict__ bps, const float* __restrict__ bbb,
    float* __restrict__ Cps, float* __restrict__ Cbb)
{
    extern __shared__ char smem[];
    int mt = blockIdx.x >> 1;
    if ((blockIdx.x & 1) == 0)
        gemm_body<25, 0, 0>(A, Bsp, bps, bbb, Cps, Cbb, smem, mt);
    else
        gemm_body<24, 200, 51200>(A, Bsp, bps, bbb, Cps, Cbb, smem, mt);
}

// ---------------- Bilinear PS-ROI sample ----------------
__device__ __forceinline__ void ps_sample4(const float* __restrict__ map,
                                           float y, float x, int cbase, float v[4])
{
    float y0f = floorf(y), x0f = floorf(x);
    float wy = y - y0f, wx = x - x0f;
    int y0 = (int)y0f; y0 = min(max(y0, 0), 159);
    int y1c = min(y0 + 1, 159);
    int x0 = (int)x0f; x0 = min(max(x0, 0), 159);
    int x1c = min(x0 + 1, 159);

    const float* p00 = map + (size_t)(y0 * 160 + x0) * 196 + cbase;
    const float* p01 = map + (size_t)(y0 * 160 + x1c) * 196 + cbase;
    const float* p10 = map + (size_t)(y1c * 160 + x0) * 196 + cbase;
    const float* p11 = map + (size_t)(y1c * 160 + x1c) * 196 + cbase;

    float w00 = (1.0f - wy) * (1.0f - wx);
    float w01 = (1.0f - wy) * wx;
    float w10 = wy * (1.0f - wx);
    float w11 = wy * wx;
#pragma unroll
    for (int p = 0; p < 4; p++) {
        v[p] = p00[p * 49] * w00 + p01[p * 49] * w01 +
               p10[p * 49] * w10 + p11[p * 49] * w11;
    }
}

__device__ __forceinline__ void roi_geom(const float* roi, int t,
                                         float& y, float& x, int& cb)
{
    float x1 = roi[1] * 0.125f;
    float yy1 = roi[2] * 0.125f;
    float x2 = roi[3] * 0.125f;
    float y2 = roi[4] * 0.125f;
    float bw = __fdiv_rn(x2 - x1, 7.0f);
    float bh = __fdiv_rn(y2 - yy1, 7.0f);
    int yI = t / 14, xI = t % 14;
    int i = yI >> 1, sy = yI & 1;
    int j = xI >> 1, sx = xI & 1;
    y = __fmaf_rn((float)i + (sy ? 0.75f : 0.25f), bh, yy1);
    x = __fmaf_rn((float)j + (sx ? 0.75f : 0.25f), bw, x1);
    cb = i * 7 + j;
}

// ---------------- fused: pooled4(rois 0..299) + proposal transform ----------------
__global__ __launch_bounds__(256) void pooled_prop_kernel(
    const float* __restrict__ rois,   // [300][5]
    const float* __restrict__ map,    // bb_map
    float* __restrict__ o_bb,         // [600][4] (rows 0..299)
    float* __restrict__ roisall,      // [600][5]
    float* __restrict__ out_roisall)  // d_out rois_all
{
    int r = blockIdx.x;
    const float* roi = rois + (size_t)r * 5;
    int t = threadIdx.x;
    float v[4] = {0.f, 0.f, 0.f, 0.f};
    if (t < 196) {
        float y, x; int cb;
        roi_geom(roi, t, y, x, cb);
        ps_sample4(map, y, x, cb, v);
    }

    __shared__ float red[4][256];
    __shared__ float s_off[4];
#pragma unroll
    for (int p = 0; p < 4; p++) red[p][t] = v[p];
    __syncthreads();
    for (int s = 128; s > 0; s >>= 1) {
        if (t < s) {
#pragma unroll
            for (int p = 0; p < 4; p++) red[p][t] += red[p][t + s];
        }
        __syncthreads();
    }
    if (t < 4) {
        float val = __fdiv_rn(red[t][0], 196.0f);
        o_bb[(size_t)r * 4 + t] = val;
        s_off[t] = val;
    }
    if (t < 5) {
        float val = roi[t];
        roisall[(size_t)r * 5 + t] = val;
        out_roisall[(size_t)r * 5 + t] = val;
    }
    __syncthreads();

    if (t == 0) {
        float x1 = roi[1], y1 = roi[2], x2 = roi[3], y2 = roi[4];
        float w = x2 - x1 + 1.0f, h = y2 - y1 + 1.0f;
        float cx = x1 + 0.5f * w, cy = y1 + 0.5f * h;
        float dx = s_off[0], dy = s_off[1], dw = s_off[2], dh = s_off[3];
        float pcx = dx * w + cx, pcy = dy * h + cy;
        float edw = (float)exp((double)dw);
        float edh = (float)exp((double)dh);
        float pw = edw * w, ph = edh * h;
        float px1 = pcx - 0.5f * pw, py1 = pcy - 0.5f * ph;
        float px2 = pcx + 0.5f * pw, py2 = pcy + 0.5f * ph;
        px1 = fminf(fmaxf(px1, 0.0f), 1279.0f);
        py1 = fminf(fmaxf(py1, 0.0f), 1279.0f);
        px2 = fminf(fmaxf(px2, 0.0f), 1279.0f);
        py2 = fminf(fmaxf(py2, 0.0f), 1279.0f);
        int rr = 300 + r;
        float vals[5] = {0.0f, px1, py1, px2, py2};
#pragma unroll
        for (int c = 0; c < 5; c++) {
            roisall[(size_t)rr * 5 + c] = vals[c];
            out_roisall[(size_t)rr * 5 + c] = vals[c];
        }
    }
}

// ---------------- roi_main: grid 900 ----------------------------------------------
// blocks 0..599   : cls/score/mask for roi b
// blocks 600..899 : bbox pooling for roi 300 + (b-600)
__global__ __launch_bounds__(256) void roi_main_kernel(
    const float* __restrict__ roisall,
    const float* __restrict__ psmap,
    const float* __restrict__ bbmap,
    float* __restrict__ out_cls,
    float* __restrict__ out_res,
    float* __restrict__ out_score,
    float* __restrict__ out_mask,
    float* __restrict__ o_bb,
    float* __restrict__ scores)
{
    int b = blockIdx.x;
    int t = threadIdx.x;
    __shared__ float red[4][256];

    if (b >= 600) {
        // ---- bbox pooling for proposal roi ----
        int r = 300 + (b - 600);
        const float* roi = roisall + (size_t)r * 5;
        float vb[4] = {0.f, 0.f, 0.f, 0.f};
        if (t < 196) {
            float y, x; int cb;
            roi_geom(roi, t, y, x, cb);
            ps_sample4(bbmap, y, x, cb, vb);
        }
#pragma unroll
        for (int p = 0; p < 4; p++) red[p][t] = vb[p];
        __syncthreads();
        for (int s = 128; s > 0; s >>= 1) {
            if (t < s) {
#pragma unroll
                for (int p = 0; p < 4; p++) red[p][t] += red[p][t + s];
            }
            __syncthreads();
        }
        if (t < 4) o_bb[(size_t)r * 4 + t] = __fdiv_rn(red[t][0], 196.0f);
        return;
    }

    // ---- cls / score / mask ----
    int r = b;
    const float* roi = roisall + (size_t)r * 5;
    float v[4] = {0.f, 0.f, 0.f, 0.f};
    float cm0 = 0.f, cm1 = 0.f;
    if (t < 196) {
        float y, x; int cb;
        roi_geom(roi, t, y, x, cb);
        ps_sample4(psmap, y, x, cb, v);
        cm0 = fmaxf(v[0], v[2]);
        cm1 = fmaxf(v[1], v[3]);
    }
    __shared__ int s_res;
    red[0][t] = cm0;
    red[1][t] = cm1;
    __syncthreads();
    for (int s = 128; s > 0; s >>= 1) {
        if (t < s) {
            red[0][t] += red[0][t + s];
            red[1][t] += red[1][t + s];
        }
        __syncthreads();
    }
    if (t == 0) {
        float a0 = __fdiv_rn(red[0][0], 196.0f);
        float a1 = __fdiv_rn(red[1][0], 196.0f);
        double m = (a0 > a1) ? (double)a0 : (double)a1;
        double e0 = exp((double)a0 - m);
        double e1 = exp((double)a1 - m);
        double inv = 1.0 / (e0 + e1);
        float c0 = (float)(e0 * inv);
        float c1 = (float)(e1 * inv);
        int res = (c1 > c0) ? 1 : 0;
        float sc = fmaxf(c0, c1);
        out_cls[(size_t)r * 2 + 0] = c0;
        out_cls[(size_t)r * 2 + 1] = c1;
        out_res[r] = (float)res;
        out_score[r] = sc;
        scores[r] = sc;
        s_res = res;
    }
    __syncthreads();

    if (t < 196) {
        int copy = s_res;
        float m0 = v[copy], m1 = v[2 + copy];
        float mm = fmaxf(m0, m1);
        float e0 = expf(m0 - mm);
        float e1 = expf(m1 - mm);
        float s = e0 + e1;
        out_mask[(size_t)r * 392 + t * 2 + 0] = __fdiv_rn(e0, s);
        out_mask[(size_t)r * 392 + t * 2 + 1] = __fdiv_rn(e1, s);
    }
}

// ---------------- NMS ----------------
__global__ __launch_bounds__(640) void nms_kernel(
    const float* __restrict__ roisall,
    const float* __restrict__ scores,
    float* __restrict__ out_keep)
{
    __shared__ float s_sc[600];
    __shared__ int s_ord[600];
    __shared__ float bxs[600 * 4];
    __shared__ float s_area[600];
    __shared__ unsigned char s_kept[600];

    int t = threadIdx.x;
    if (t < 600) s_sc[t] = scores[t];
    __syncthreads();

    if (t < 600) {
        float si = s_sc[t];
        int cnt = 0;
        for (int j = 0; j < 600; j++) {
            float sj = s_sc[j];
            cnt += (sj > si) || (sj == si && j < t);
        }
        s_ord[cnt] = t;
    }
    __syncthreads();

    float bx1 = 0.f, by1 = 0.f, bx2 = 0.f, by2 = 0.f, myArea = 0.f;
    bool kept_self = false;
    if (t < 600) {
        int o = s_ord[t];
        bx1 = roisall[(size_t)o * 5 + 1];
        by1 = roisall[(size_t)o * 5 + 2];
        bx2 = roisall[(size_t)o * 5 + 3];
        by2 = roisall[(size_t)o * 5 + 4];
        myArea = fmaxf(bx2 - bx1, 0.0f) * fmaxf(by2 - by1, 0.0f);
        bxs[t * 4 + 0] = bx1;
        bxs[t * 4 + 1] = by1;
        bxs[t * 4 + 2] = bx2;
        bxs[t * 4 + 3] = by2;
        s_area[t] = myArea;
    }
    __syncthreads();

    for (int i = 0; i < 600; i++) {
        bool p = false;
        if (t < i && kept_self) {
            float cx1 = bxs[i * 4 + 0], cy1 = bxs[i * 4 + 1];
            float cx2 = bxs[i * 4 + 2], cy2 = bxs[i * 4 + 3];
            float ix1 = fmaxf(cx1, bx1), iy1 = fmaxf(cy1, by1);
            float ix2 = fminf(cx2, bx2), iy2 = fminf(cy2, by2);
            float inter = fmaxf(ix2 - ix1, 0.0f) * fmaxf(iy2 - iy1, 0.0f);
            float denom = s_area[i] + myArea - inter + 1e-8f;
            float iou = __fdiv_rn(inter, denom);
            p = iou > 0.3f;
        }
        int any = __syncthreads_or((int)p);
        if (t == i) kept_self = !any;
    }

    if (t < 600) s_kept[t] = kept_self ? 1 : 0;
    __syncthreads();

    if (t == 0) {
        int rc = 0;
        for (int p2 = 0; p2 < 600 && rc < 300; p2++) {
            if (s_kept[p2]) out_keep[rc++] = (float)s_ord[p2];
        }
        for (; rc < 300; rc++) out_keep[rc] = -1.0f;
    }
}

// ---------------- launch ----------------
extern "C" void kernel_launch(void* const* d_in, const int* in_sizes, int n_in,
                              void* d_out, int out_size)
{
    const float* feat = (const float*)d_in[0];
    const float* Wps  = (const float*)d_in[1];
    const float* bps  = (const float*)d_in[2];
    const float* Wbb  = (const float*)d_in[3];
    const float* bbb  = (const float*)d_in[4];
    const float* rois = (const float*)d_in[5];

    float* out = (float*)d_out;
    float* o_cls  = out;
    float* o_res  = out + 1200;
    float* o_sc   = out + 1800;
    float* o_mask = out + 2400;
    float* o_ra   = out + 237600;
    float* o_bb   = out + 240600;
    float* o_keep = out + 243000;

    float *p_ps, *p_bb, *p_ra, *p_sc;
    uint4 *p_B;
    cudaGetSymbolAddress((void**)&p_ps, g_ps);
    cudaGetSymbolAddress((void**)&p_bb, g_bb);
    cudaGetSymbolAddress((void**)&p_ra, g_roisall);
    cudaGetSymbolAddress((void**)&p_sc, g_scores);
    cudaGetSymbolAddress((void**)&p_B, g_Bsp);

    cudaFuncSetAttribute(gemm_mma, cudaFuncAttributeMaxDynamicSharedMemorySize,
                         GEMM_SMEM);

    // 0. pre-split W (tiny)
    prep_B<<<392, 256>>>(Wps, Wbb, p_B);
    // 1. feature maps (fp32 A streamed, packed split at consumption)
    gemm_mma<<<400, 256, GEMM_SMEM>>>(feat, p_B, bps, bbb, p_ps, p_bb);
    // 2. pooled offsets (== bbox[0:300]) + proposal transform, fused
    pooled_prop_kernel<<<300, 256>>>(rois, p_bb, o_bb, p_ra, o_ra);
    // 3. cls/score/mask (600 blocks) + bbox pooling for proposals (300 blocks)
    roi_main_kernel<<<900, 256>>>(p_ra, p_ps, p_bb, o_cls, o_res, o_sc,
                                  o_mask, o_bb, p_sc);
    // 4. NMS
    nms_kernel<<<1, 640>>>(p_ra, p_sc, o_keep);
}

// round 14
// speedup vs baseline: 1.0138x; 1.0138x over previous
#include <cuda_runtime.h>
#include <cuda_fp16.h>
#include <math.h>
#include <stdint.h>
#include <float.h>

// ---------------- Scratch (device globals; no allocation allowed) ----------------
__device__ float g_ps[25600 * 196];     // ps_map
__device__ float g_bb[25600 * 196];     // bb_map
__device__ float g_roisall[600 * 5];
__device__ float g_scores[600];
__device__ uint4 g_Bsp[100352];         // 1.6 MB pre-split W (frag order)

#define A_SCALE 64.0f
#define B_SCALE 1024.0f
#define INV_SCALE (1.0f / 65536.0f)

// ================= helpers =================
__device__ __forceinline__ uint32_t smem_u32(const void* p) {
    uint32_t a;
    asm("{ .reg .u64 t; cvta.to.shared.u64 t, %1; cvt.u32.u64 %0, t; }" : "=r"(a) : "l"(p));
    return a;
}
__device__ __forceinline__ void cpa16(uint32_t saddr, const void* gptr) {
    asm volatile("cp.async.cg.shared.global [%0], [%1], 16;" :: "r"(saddr), "l"(gptr));
}
#define CP_COMMIT() asm volatile("cp.async.commit_group;" ::: "memory")
#define CP_WAIT1()  asm volatile("cp.async.wait_group 1;" ::: "memory")
#define CP_WAIT0()  asm volatile("cp.async.wait_group 0;" ::: "memory")

__device__ __forceinline__ void splith(float x, __half& h, __half& l) {
    h = __float2half_rn(x);
    l = __float2half_rn(x - __half2float(h));
}
__device__ __forceinline__ uint32_t packh2(__half a, __half b) {
    __half2 v = __halves2half2(a, b);
    return *reinterpret_cast<uint32_t*>(&v);
}
// scalar split of a float2 (pre-scaled) into packed hi / packed lo half2
// (round-12 form: short independent per-element chains — schedules best)
__device__ __forceinline__ void split2(float2 u, uint32_t& hi, uint32_t& lo) {
    __half ha, la, hb, lb;
    splith(u.x * A_SCALE, ha, la);
    splith(u.y * A_SCALE, hb, lb);
    hi = packh2(ha, hb);
    lo = packh2(la, lb);
}

// f32-accumulator mma (dominant hi*hi pass)
__device__ __forceinline__ void mma_f16(float c[4], const uint32_t a[4],
                                        uint32_t b0, uint32_t b1) {
    asm volatile(
        "mma.sync.aligned.m16n8k16.row.col.f32.f16.f16.f32 "
        "{%0,%1,%2,%3}, {%4,%5,%6,%7}, {%8,%9}, {%0,%1,%2,%3};"
        : "+f"(c[0]), "+f"(c[1]), "+f"(c[2]), "+f"(c[3])
        : "r"(a[0]), "r"(a[1]), "r"(a[2]), "r"(a[3]), "r"(b0), "r"(b1));
}
// f16-accumulator mma (small correction passes)
__device__ __forceinline__ void mma_f16acc(uint32_t c[2], const uint32_t a[4],
                                           uint32_t b0, uint32_t b1) {
    asm volatile(
        "mma.sync.aligned.m16n8k16.row.col.f16.f16.f16.f16 "
        "{%0,%1}, {%2,%3,%4,%5}, {%6,%7}, {%0,%1};"
        : "+r"(c[0]), "+r"(c[1])
        : "r"(a[0]), "r"(a[1]), "r"(a[2]), "r"(a[3]), "r"(b0), "r"(b1));
}

// ================= prep_B: W -> fp16 hi/lo frag order ================
__global__ __launch_bounds__(256) void prep_B(const float* __restrict__ Wps,
                                              const float* __restrict__ Wbb,
                                              uint4* __restrict__ Bsp)
{
    int i = blockIdx.x * 256 + threadIdx.x;          // 0 .. 100,351
    if (i >= 100352) return;
    int ntc, nbase, base;
    if (i < 51200) { ntc = 25; nbase = 0; base = 0; }
    else           { ntc = 24; nbase = 200; base = 51200; }
    int li = i - base;
    int lane = li & 31;
    int j = li >> 5;
    int nt = j % ntc; j /= ntc;
    int ks = j & 1;
    int kt = j >> 1;
    int g = lane >> 2, t = lane & 3;
    int n = nbase + nt * 8 + g;
    int k = kt * 32 + ks * 16 + 2 * t;

    const float* W = (n < 196) ? Wps : Wbb;
    int nn = (n < 196) ? n : n - 196;
    float w0 = W[(size_t)k * 196 + nn] * B_SCALE;
    float w1 = W[(size_t)(k + 1) * 196 + nn] * B_SCALE;
    float w2 = W[(size_t)(k + 8) * 196 + nn] * B_SCALE;
    float w3 = W[(size_t)(k + 9) * 196 + nn] * B_SCALE;

    __half h0, l0, h1, l1, h2, l2, h3, l3;
    splith(w0, h0, l0); splith(w1, h1, l1);
    splith(w2, h2, l2); splith(w3, h3, l3);
    Bsp[i] = make_uint4(packh2(h0, h1), packh2(h2, h3),
                        packh2(l0, l1), packh2(l2, l3));
}

// ================= GEMM: fp16x3 mma, fp32 A via cp.async, split at consumption ====
#define ASTRIDE 36
#define ABUF (128 * ASTRIDE * 4)           // 18432 B per A stage
#define BBUF 25600
#define GEMM_SMEM (3 * ABUF + 3 * BBUF)    // 132096

template<int NTC, int NBASE, int BOFF>
__device__ __forceinline__ void gemm_body(
    const float* __restrict__ A, const uint4* __restrict__ Bsp,
    const float* __restrict__ bps, const float* __restrict__ bbb,
    float* __restrict__ Cps, float* __restrict__ Cbb, char* smem, int mt)
{
    const int tid = threadIdx.x;
    const int lane = tid & 31;
    const int wid = tid >> 5;
    const int g = lane >> 2;
    const int t = lane & 3;
    const uint32_t sbase = smem_u32(smem);

    float chh[NTC][4];
    uint32_t ccr[NTC][2];
#pragma unroll
    for (int nt = 0; nt < NTC; nt++) {
#pragma unroll
        for (int j = 0; j < 4; j++) chh[nt][j] = 0.0f;
        ccr[nt][0] = 0u;
        ccr[nt][1] = 0u;
    }

    const float* Abase = A + (size_t)mt * 128 * 1024;

    auto copy_stage = [&](int s, int buf) {
        uint32_t sa = sbase + buf * ABUF;
        const float* ga = Abase + s * 32;
#pragma unroll
        for (int i = 0; i < 4; i++) {
            int c = tid + i * 256;          // 0..1023
            int row = c >> 3, q = c & 7;
            cpa16(sa + row * (ASTRIDE * 4) + q * 16,
                  ga + (size_t)row * 1024 + q * 4);
        }
        const uint4* gb = Bsp + BOFF + (size_t)s * (NTC * 64);
        uint32_t sB = sbase + 3 * ABUF + buf * BBUF;
#pragma unroll
        for (int i = 0; i < 6; i++) {
            int o = tid + i * 256;
            cpa16(sB + o * 16, gb + o);
        }
        if (NTC == 25 && tid < 64) {
            int o = tid + 1536;
            cpa16(sB + o * 16, gb + o);
        }
        CP_COMMIT();
    };

    copy_stage(0, 0);
    copy_stage(1, 1);

    const int r0 = wid * 16 + g;

    for (int s = 0; s < 32; ++s) {
        if (s < 31) CP_WAIT1(); else CP_WAIT0();
        __syncthreads();
        if (s + 2 < 32) copy_stage(s + 2, (s + 2) % 3);

        const int buf = s % 3;
        const float* Af = reinterpret_cast<const float*>(smem + buf * ABUF);
        const uint4* Bs = reinterpret_cast<const uint4*>(smem + 3 * ABUF + buf * BBUF);

#pragma unroll
        for (int ks = 0; ks < 2; ks++) {
            const int k0 = ks * 16 + 2 * t;
            float2 u0 = *reinterpret_cast<const float2*>(&Af[r0 * ASTRIDE + k0]);
            float2 u1 = *reinterpret_cast<const float2*>(&Af[r0 * ASTRIDE + k0 + 8]);
            float2 u2 = *reinterpret_cast<const float2*>(&Af[(r0 + 8) * ASTRIDE + k0]);
            float2 u3 = *reinterpret_cast<const float2*>(&Af[(r0 + 8) * ASTRIDE + k0 + 8]);
            uint32_t ah[4], al[4];
            split2(u0, ah[0], al[0]);   // (g,   k0|k0+1)
            split2(u2, ah[1], al[1]);   // (g+8, k0|k0+1)
            split2(u1, ah[2], al[2]);   // (g,   k0+8|k0+9)
            split2(u3, ah[3], al[3]);   // (g+8, k0+8|k0+9)
#pragma unroll
            for (int nt = 0; nt < NTC; nt++) {
                uint4 q = Bs[(ks * NTC + nt) * 32 + lane];
                mma_f16acc(ccr[nt], al, q.x, q.y);   // lo_a * hi_b (f16 acc)
                mma_f16acc(ccr[nt], ah, q.z, q.w);   // hi_a * lo_b (f16 acc)
                mma_f16(chh[nt], ah, q.x, q.y);      // hi_a * hi_b (f32 acc)
            }
        }
    }

    const int rg = mt * 128 + r0;
#pragma unroll
    for (int nt = 0; nt < NTC; nt++) {
        int gc = NBASE + nt * 8 + t * 2;
        float bias0, bias1;
        float* Cout;
        int cc;
        if (gc < 196) { bias0 = bps[gc]; bias1 = bps[gc + 1]; Cout = Cps; cc = gc; }
        else { bias0 = bbb[gc - 196]; bias1 = bbb[gc - 195]; Cout = Cbb; cc = gc - 196; }
        __half2 q01 = *reinterpret_cast<__half2*>(&ccr[nt][0]);
        __half2 q23 = *reinterpret_cast<__half2*>(&ccr[nt][1]);
        float2 cr01 = __half22float2(q01);
        float2 cr23 = __half22float2(q23);
        float2 w0 = make_float2((chh[nt][0] + cr01.x) * INV_SCALE + bias0,
                                (chh[nt][1] + cr01.y) * INV_SCALE + bias1);
        float2 w1 = make_float2((chh[nt][2] + cr23.x) * INV_SCALE + bias0,
                                (chh[nt][3] + cr23.y) * INV_SCALE + bias1);
        *reinterpret_cast<float2*>(&Cout[(size_t)rg * 196 + cc]) = w0;
        *reinterpret_cast<float2*>(&Cout[(size_t)(rg + 8) * 196 + cc]) = w1;
    }
}

__global__ __launch_bounds__(256, 1) void gemm_mma(
    const float* __restrict__ A, const uint4* __restrict__ Bsp,
    const float* __restrict__ bps, const float* __restrict__ bbb,
    float* __restrict__ Cps, float* __restrict__ Cbb)
{
    extern __shared__ char smem[];
    int mt = blockIdx.x >> 1;
    if ((blockIdx.x & 1) == 0)
        gemm_body<25, 0, 0>(A, Bsp, bps, bbb, Cps, Cbb, smem, mt);
    else
        gemm_body<24, 200, 51200>(A, Bsp, bps, bbb, Cps, Cbb, smem, mt);
}

// ---------------- Bilinear PS-ROI sample ----------------
__device__ __forceinline__ void ps_sample4(const float* __restrict__ map,
                                           float y, float x, int cbase, float v[4])
{
    float y0f = floorf(y), x0f = floorf(x);
    float wy = y - y0f, wx = x - x0f;
    int y0 = (int)y0f; y0 = min(max(y0, 0), 159);
    int y1c = min(y0 + 1, 159);
    int x0 = (int)x0f; x0 = min(max(x0, 0), 159);
    int x1c = min(x0 + 1, 159);

    const float* p00 = map + (size_t)(y0 * 160 + x0) * 196 + cbase;
    const float* p01 = map + (size_t)(y0 * 160 + x1c) * 196 + cbase;
    const float* p10 = map + (size_t)(y1c * 160 + x0) * 196 + cbase;
    const float* p11 = map + (size_t)(y1c * 160 + x1c) * 196 + cbase;

    float w00 = (1.0f - wy) * (1.0f - wx);
    float w01 = (1.0f - wy) * wx;
    float w10 = wy * (1.0f - wx);
    float w11 = wy * wx;
#pragma unroll
    for (int p = 0; p < 4; p++) {
        v[p] = p00[p * 49] * w00 + p01[p * 49] * w01 +
               p10[p * 49] * w10 + p11[p * 49] * w11;
    }
}

__device__ __forceinline__ void roi_geom(const float* roi, int t,
                                         float& y, float& x, int& cb)
{
    float x1 = roi[1] * 0.125f;
    float yy1 = roi[2] * 0.125f;
    float x2 = roi[3] * 0.125f;
    float y2 = roi[4] * 0.125f;
    float bw = __fdiv_rn(x2 - x1, 7.0f);
    float bh = __fdiv_rn(y2 - yy1, 7.0f);
    int yI = t / 14, xI = t % 14;
    int i = yI >> 1, sy = yI & 1;
    int j = xI >> 1, sx = xI & 1;
    y = __fmaf_rn((float)i + (sy ? 0.75f : 0.25f), bh, yy1);
    x = __fmaf_rn((float)j + (sx ? 0.75f : 0.25f), bw, x1);
    cb = i * 7 + j;
}

// ---------------- fused: pooled4(rois 0..299) + proposal transform ----------------
__global__ __launch_bounds__(256) void pooled_prop_kernel(
    const float* __restrict__ rois,   // [300][5]
    const float* __restrict__ map,    // bb_map
    float* __restrict__ o_bb,         // [600][4] (rows 0..299)
    float* __restrict__ roisall,      // [600][5]
    float* __restrict__ out_roisall)  // d_out rois_all
{
    int r = blockIdx.x;
    const float* roi = rois + (size_t)r * 5;
    int t = threadIdx.x;
    float v[4] = {0.f, 0.f, 0.f, 0.f};
    if (t < 196) {
        float y, x; int cb;
        roi_geom(roi, t, y, x, cb);
        ps_sample4(map, y, x, cb, v);
    }

    __shared__ float red[4][256];
    __shared__ float s_off[4];
#pragma unroll
    for (int p = 0; p < 4; p++) red[p][t] = v[p];
    __syncthreads();
    for (int s = 128; s > 0; s >>= 1) {
        if (t < s) {
#pragma unroll
            for (int p = 0; p < 4; p++) red[p][t] += red[p][t + s];
        }
        __syncthreads();
    }
    if (t < 4) {
        float val = __fdiv_rn(red[t][0], 196.0f);
        o_bb[(size_t)r * 4 + t] = val;
        s_off[t] = val;
    }
    if (t < 5) {
        float val = roi[t];
        roisall[(size_t)r * 5 + t] = val;
        out_roisall[(size_t)r * 5 + t] = val;
    }
    __syncthreads();

    if (t == 0) {
        float x1 = roi[1], y1 = roi[2], x2 = roi[3], y2 = roi[4];
        float w = x2 - x1 + 1.0f, h = y2 - y1 + 1.0f;
        float cx = x1 + 0.5f * w, cy = y1 + 0.5f * h;
        float dx = s_off[0], dy = s_off[1], dw = s_off[2], dh = s_off[3];
        float pcx = dx * w + cx, pcy = dy * h + cy;
        float edw = (float)exp((double)dw);
        float edh = (float)exp((double)dh);
        float pw = edw * w, ph = edh * h;
        float px1 = pcx - 0.5f * pw, py1 = pcy - 0.5f * ph;
        float px2 = pcx + 0.5f * pw, py2 = pcy + 0.5f * ph;
        px1 = fminf(fmaxf(px1, 0.0f), 1279.0f);
        py1 = fminf(fmaxf(py1, 0.0f), 1279.0f);
        px2 = fminf(fmaxf(px2, 0.0f), 1279.0f);
        py2 = fminf(fmaxf(py2, 0.0f), 1279.0f);
        int rr = 300 + r;
        float vals[5] = {0.0f, px1, py1, px2, py2};
#pragma unroll
        for (int c = 0; c < 5; c++) {
            roisall[(size_t)rr * 5 + c] = vals[c];
            out_roisall[(size_t)rr * 5 + c] = vals[c];
        }
    }
}

// ---------------- roi_main: grid 900 ----------------------------------------------
// blocks 0..599   : cls/score/mask for roi b
// blocks 600..899 : bbox pooling for roi 300 + (b-600)
__global__ __launch_bounds__(256) void roi_main_kernel(
    const float* __restrict__ roisall,
    const float* __restrict__ psmap,
    const float* __restrict__ bbmap,
    float* __restrict__ out_cls,
    float* __restrict__ out_res,
    float* __restrict__ out_score,
    float* __restrict__ out_mask,
    float* __restrict__ o_bb,
    float* __restrict__ scores)
{
    int b = blockIdx.x;
    int t = threadIdx.x;
    __shared__ float red[4][256];

    if (b >= 600) {
        int r = 300 + (b - 600);
        const float* roi = roisall + (size_t)r * 5;
        float vb[4] = {0.f, 0.f, 0.f, 0.f};
        if (t < 196) {
            float y, x; int cb;
            roi_geom(roi, t, y, x, cb);
            ps_sample4(bbmap, y, x, cb, vb);
        }
#pragma unroll
        for (int p = 0; p < 4; p++) red[p][t] = vb[p];
        __syncthreads();
        for (int s = 128; s > 0; s >>= 1) {
            if (t < s) {
#pragma unroll
                for (int p = 0; p < 4; p++) red[p][t] += red[p][t + s];
            }
            __syncthreads();
        }
        if (t < 4) o_bb[(size_t)r * 4 + t] = __fdiv_rn(red[t][0], 196.0f);
        return;
    }

    int r = b;
    const float* roi = roisall + (size_t)r * 5;
    float v[4] = {0.f, 0.f, 0.f, 0.f};
    float cm0 = 0.f, cm1 = 0.f;
    if (t < 196) {
        float y, x; int cb;
        roi_geom(roi, t, y, x, cb);
        ps_sample4(psmap, y, x, cb, v);
        cm0 = fmaxf(v[0], v[2]);
        cm1 = fmaxf(v[1], v[3]);
    }
    __shared__ int s_res;
    red[0][t] = cm0;
    red[1][t] = cm1;
    __syncthreads();
    for (int s = 128; s > 0; s >>= 1) {
        if (t < s) {
            red[0][t] += red[0][t + s];
            red[1][t] += red[1][t + s];
        }
        __syncthreads();
    }
    if (t == 0) {
        float a0 = __fdiv_rn(red[0][0], 196.0f);
        float a1 = __fdiv_rn(red[1][0], 196.0f);
        double m = (a0 > a1) ? (double)a0 : (double)a1;
        double e0 = exp((double)a0 - m);
        double e1 = exp((double)a1 - m);
        double inv = 1.0 / (e0 + e1);
        float c0 = (float)(e0 * inv);
        float c1 = (float)(e1 * inv);
        int res = (c1 > c0) ? 1 : 0;
        float sc = fmaxf(c0, c1);
        out_cls[(size_t)r * 2 + 0] = c0;
        out_cls[(size_t)r * 2 + 1] = c1;
        out_res[r] = (float)res;
        out_score[r] = sc;
        scores[r] = sc;
        s_res = res;
    }
    __syncthreads();

    if (t < 196) {
        int copy = s_res;
        float m0 = v[copy], m1 = v[2 + copy];
        float mm = fmaxf(m0, m1);
        float e0 = expf(m0 - mm);
        float e1 = expf(m1 - mm);
        float s = e0 + e1;
        out_mask[(size_t)r * 392 + t * 2 + 0] = __fdiv_rn(e0, s);
        out_mask[(size_t)r * 392 + t * 2 + 1] = __fdiv_rn(e1, s);
    }
}

// ---------------- NMS ----------------
__global__ __launch_bounds__(640) void nms_kernel(
    const float* __restrict__ roisall,
    const float* __restrict__ scores,
    float* __restrict__ out_keep)
{
    __shared__ float s_sc[600];
    __shared__ int s_ord[600];
    __shared__ float bxs[600 * 4];
    __shared__ float s_area[600];
    __shared__ unsigned char s_kept[600];

    int t = threadIdx.x;
    if (t < 600) s_sc[t] = scores[t];
    __syncthreads();

    if (t < 600) {
        float si = s_sc[t];
        int cnt = 0;
        for (int j = 0; j < 600; j++) {
            float sj = s_sc[j];
            cnt += (sj > si) || (sj == si && j < t);
        }
        s_ord[cnt] = t;
    }
    __syncthreads();

    float bx1 = 0.f, by1 = 0.f, bx2 = 0.f, by2 = 0.f, myArea = 0.f;
    bool kept_self = false;
    if (t < 600) {
        int o = s_ord[t];
        bx1 = roisall[(size_t)o * 5 + 1];
        by1 = roisall[(size_t)o * 5 + 2];
        bx2 = roisall[(size_t)o * 5 + 3];
        by2 = roisall[(size_t)o * 5 + 4];
        myArea = fmaxf(bx2 - bx1, 0.0f) * fmaxf(by2 - by1, 0.0f);
        bxs[t * 4 + 0] = bx1;
        bxs[t * 4 + 1] = by1;
        bxs[t * 4 + 2] = bx2;
        bxs[t * 4 + 3] = by2;
        s_area[t] = myArea;
    }
    __syncthreads();

    for (int i = 0; i < 600; i++) {
        bool p = false;
        if (t < i && kept_self) {
            float cx1 = bxs[i * 4 + 0], cy1 = bxs[i * 4 + 1];
            float cx2 = bxs[i * 4 + 2], cy2 = bxs[i * 4 + 3];
            float ix1 = fmaxf(cx1, bx1), iy1 = fmaxf(cy1, by1);
            float ix2 = fminf(cx2, bx2), iy2 = fminf(cy2, by2);
            float inter = fmaxf(ix2 - ix1, 0.0f) * fmaxf(iy2 - iy1, 0.0f);
            float denom = s_area[i] + myArea - inter + 1e-8f;
            float iou = __fdiv_rn(inter, denom);
            p = iou > 0.3f;
        }
        int any = __syncthreads_or((int)p);
        if (t == i) kept_self = !any;
    }

    if (t < 600) s_kept[t] = kept_self ? 1 : 0;
    __syncthreads();

    if (t == 0) {
        int rc = 0;
        for (int p2 = 0; p2 < 600 && rc < 300; p2++) {
            if (s_kept[p2]) out_keep[rc++] = (float)s_ord[p2];
        }
        for (; rc < 300; rc++) out_keep[rc] = -1.0f;
    }
}

// ---------------- launch ----------------
extern "C" void kernel_launch(void* const* d_in, const int* in_sizes, int n_in,
                              void* d_out, int out_size)
{
    const float* feat = (const float*)d_in[0];
    const float* Wps  = (const float*)d_in[1];
    const float* bps  = (const float*)d_in[2];
    const float* Wbb  = (const float*)d_in[3];
    const float* bbb  = (const float*)d_in[4];
    const float* rois = (const float*)d_in[5];

    float* out = (float*)d_out;
    float* o_cls  = out;
    float* o_res  = out + 1200;
    float* o_sc   = out + 1800;
    float* o_mask = out + 2400;
    float* o_ra   = out + 237600;
    float* o_bb   = out + 240600;
    float* o_keep = out + 243000;

    float *p_ps, *p_bb, *p_ra, *p_sc;
    uint4 *p_B;
    cudaGetSymbolAddress((void**)&p_ps, g_ps);
    cudaGetSymbolAddress((void**)&p_bb, g_bb);
    cudaGetSymbolAddress((void**)&p_ra, g_roisall);
    cudaGetSymbolAddress((void**)&p_sc, g_scores);
    cudaGetSymbolAddress((void**)&p_B, g_Bsp);

    cudaFuncSetAttribute(gemm_mma, cudaFuncAttributeMaxDynamicSharedMemorySize,
                         GEMM_SMEM);

    // 0. pre-split W (tiny)
    prep_B<<<392, 256>>>(Wps, Wbb, p_B);
    // 1. feature maps (fp32 A streamed, scalar split at consumption)
    gemm_mma<<<400, 256, GEMM_SMEM>>>(feat, p_B, bps, bbb, p_ps, p_bb);
    // 2. pooled offsets (== bbox[0:300]) + proposal transform, fused
    pooled_prop_kernel<<<300, 256>>>(rois, p_bb, o_bb, p_ra, o_ra);
    // 3. cls/score/mask (600 blocks) + bbox pooling for proposals (300 blocks)
    roi_main_kernel<<<900, 256>>>(p_ra, p_ps, p_bb, o_cls, o_res, o_sc,
                                  o_mask, o_bb, p_sc);
    // 4. NMS
    nms_kernel<<<1, 640>>>(p_ra, p_sc, o_keep);
}

// round 15
// speedup vs baseline: 1.0492x; 1.0349x over previous
#include <cuda_runtime.h>
#include <cuda_fp16.h>
#include <math.h>
#include <stdint.h>
#include <float.h>

// ---------------- Scratch (device globals; no allocation allowed) ----------------
__device__ float g_ps[25600 * 196];     // ps_map
__device__ float g_bb[25600 * 196];     // bb_map
__device__ float g_roisall[600 * 5];
__device__ float g_scores[600];
__device__ uint4 g_Bsp[100352];         // 1.6 MB pre-split W (frag order)

#define A_SCALE 64.0f
#define B_SCALE 1024.0f
#define INV_SCALE (1.0f / 65536.0f)

// ================= helpers =================
__device__ __forceinline__ uint32_t smem_u32(const void* p) {
    uint32_t a;
    asm("{ .reg .u64 t; cvta.to.shared.u64 t, %1; cvt.u32.u64 %0, t; }" : "=r"(a) : "l"(p));
    return a;
}
__device__ __forceinline__ void cpa16(uint32_t saddr, const void* gptr) {
    asm volatile("cp.async.cg.shared.global [%0], [%1], 16;" :: "r"(saddr), "l"(gptr));
}
#define CP_COMMIT() asm volatile("cp.async.commit_group;" ::: "memory")
#define CP_WAIT1()  asm volatile("cp.async.wait_group 1;" ::: "memory")
#define CP_WAIT0()  asm volatile("cp.async.wait_group 0;" ::: "memory")

__device__ __forceinline__ void splith(float x, __half& h, __half& l) {
    h = __float2half_rn(x);
    l = __float2half_rn(x - __half2float(h));
}
__device__ __forceinline__ uint32_t packh2(__half a, __half b) {
    __half2 v = __halves2half2(a, b);
    return *reinterpret_cast<uint32_t*>(&v);
}
// scalar split of a float2 (pre-scaled) into packed hi / packed lo half2
__device__ __forceinline__ void split2(float2 u, uint32_t& hi, uint32_t& lo) {
    __half ha, la, hb, lb;
    splith(u.x * A_SCALE, ha, la);
    splith(u.y * A_SCALE, hb, lb);
    hi = packh2(ha, hb);
    lo = packh2(la, lb);
}

// f32-accumulator mma (dominant hi*hi pass)
__device__ __forceinline__ void mma_f16(float c[4], const uint32_t a[4],
                                        uint32_t b0, uint32_t b1) {
    asm volatile(
        "mma.sync.aligned.m16n8k16.row.col.f32.f16.f16.f32 "
        "{%0,%1,%2,%3}, {%4,%5,%6,%7}, {%8,%9}, {%0,%1,%2,%3};"
        : "+f"(c[0]), "+f"(c[1]), "+f"(c[2]), "+f"(c[3])
        : "r"(a[0]), "r"(a[1]), "r"(a[2]), "r"(a[3]), "r"(b0), "r"(b1));
}
// f16-accumulator mma (small correction passes)
__device__ __forceinline__ void mma_f16acc(uint32_t c[2], const uint32_t a[4],
                                           uint32_t b0, uint32_t b1) {
    asm volatile(
        "mma.sync.aligned.m16n8k16.row.col.f16.f16.f16.f16 "
        "{%0,%1}, {%2,%3,%4,%5}, {%6,%7}, {%0,%1};"
        : "+r"(c[0]), "+r"(c[1])
        : "r"(a[0]), "r"(a[1]), "r"(a[2]), "r"(a[3]), "r"(b0), "r"(b1));
}

// ================= prep_B: W -> fp16 hi/lo frag order ================
__global__ __launch_bounds__(256) void prep_B(const float* __restrict__ Wps,
                                              const float* __restrict__ Wbb,
                                              uint4* __restrict__ Bsp)
{
    int i = blockIdx.x * 256 + threadIdx.x;          // 0 .. 100,351
    if (i >= 100352) return;
    int ntc, nbase, base;
    if (i < 51200) { ntc = 25; nbase = 0; base = 0; }
    else           { ntc = 24; nbase = 200; base = 51200; }
    int li = i - base;
    int lane = li & 31;
    int j = li >> 5;
    int nt = j % ntc; j /= ntc;
    int ks = j & 1;
    int kt = j >> 1;
    int g = lane >> 2, t = lane & 3;
    int n = nbase + nt * 8 + g;
    int k = kt * 32 + ks * 16 + 2 * t;

    const float* W = (n < 196) ? Wps : Wbb;
    int nn = (n < 196) ? n : n - 196;
    float w0 = W[(size_t)k * 196 + nn] * B_SCALE;
    float w1 = W[(size_t)(k + 1) * 196 + nn] * B_SCALE;
    float w2 = W[(size_t)(k + 8) * 196 + nn] * B_SCALE;
    float w3 = W[(size_t)(k + 9) * 196 + nn] * B_SCALE;

    __half h0, l0, h1, l1, h2, l2, h3, l3;
    splith(w0, h0, l0); splith(w1, h1, l1);
    splith(w2, h2, l2); splith(w3, h3, l3);
    Bsp[i] = make_uint4(packh2(h0, h1), packh2(h2, h3),
                        packh2(l0, l1), packh2(l2, l3));
}

// ================= GEMM: fp16x3 mma, fp32 A via cp.async, split at consumption ====
#define ASTRIDE 36
#define ABUF (128 * ASTRIDE * 4)           // 18432 B per A stage
#define BBUF 25600
#define GEMM_SMEM (3 * ABUF + 3 * BBUF)    // 132096

template<int NTC, int NBASE, int BOFF>
__device__ __forceinline__ void gemm_body(
    const float* __restrict__ A, const uint4* __restrict__ Bsp,
    const float* __restrict__ bps, const float* __restrict__ bbb,
    float* __restrict__ Cps, float* __restrict__ Cbb, char* smem, int mt)
{
    const int tid = threadIdx.x;
    const int lane = tid & 31;
    const int wid = tid >> 5;
    const int g = lane >> 2;
    const int t = lane & 3;
    const uint32_t sbase = smem_u32(smem);

    float chh[NTC][4];
    uint32_t ccr[NTC][2];
#pragma unroll
    for (int nt = 0; nt < NTC; nt++) {
#pragma unroll
        for (int j = 0; j < 4; j++) chh[nt][j] = 0.0f;
        ccr[nt][0] = 0u;
        ccr[nt][1] = 0u;
    }

    const float* Abase = A + (size_t)mt * 128 * 1024;

    auto copy_stage = [&](int s, int buf) {
        uint32_t sa = sbase + buf * ABUF;
        const float* ga = Abase + s * 32;
#pragma unroll
        for (int i = 0; i < 4; i++) {
            int c = tid + i * 256;          // 0..1023
            int row = c >> 3, q = c & 7;
            cpa16(sa + row * (ASTRIDE * 4) + q * 16,
                  ga + (size_t)row * 1024 + q * 4);
        }
        const uint4* gb = Bsp + BOFF + (size_t)s * (NTC * 64);
        uint32_t sB = sbase + 3 * ABUF + buf * BBUF;
#pragma unroll
        for (int i = 0; i < 6; i++) {
            int o = tid + i * 256;
            cpa16(sB + o * 16, gb + o);
        }
        if (NTC == 25 && tid < 64) {
            int o = tid + 1536;
            cpa16(sB + o * 16, gb + o);
        }
        CP_COMMIT();
    };

    copy_stage(0, 0);
    copy_stage(1, 1);

    const int r0 = wid * 16 + g;

    for (int s = 0; s < 32; ++s) {
        if (s < 31) CP_WAIT1(); else CP_WAIT0();
        __syncthreads();
        if (s + 2 < 32) copy_stage(s + 2, (s + 2) % 3);

        const int buf = s % 3;
        const float* Af = reinterpret_cast<const float*>(smem + buf * ABUF);
        const uint4* Bs = reinterpret_cast<const uint4*>(smem + 3 * ABUF + buf * BBUF);

        // hoist loads + splits for BOTH ks blocks: ks=1's split latency
        // resolves under ks=0's mma issue stream.
        uint32_t ah2[2][4], al2[2][4];
#pragma unroll
        for (int ks = 0; ks < 2; ks++) {
            const int k0 = ks * 16 + 2 * t;
            float2 u0 = *reinterpret_cast<const float2*>(&Af[r0 * ASTRIDE + k0]);
            float2 u1 = *reinterpret_cast<const float2*>(&Af[r0 * ASTRIDE + k0 + 8]);
            float2 u2 = *reinterpret_cast<const float2*>(&Af[(r0 + 8) * ASTRIDE + k0]);
            float2 u3 = *reinterpret_cast<const float2*>(&Af[(r0 + 8) * ASTRIDE + k0 + 8]);
            split2(u0, ah2[ks][0], al2[ks][0]);   // (g,   k0|k0+1)
            split2(u2, ah2[ks][1], al2[ks][1]);   // (g+8, k0|k0+1)
            split2(u1, ah2[ks][2], al2[ks][2]);   // (g,   k0+8|k0+9)
            split2(u3, ah2[ks][3], al2[ks][3]);   // (g+8, k0+8|k0+9)
        }
#pragma unroll
        for (int ks = 0; ks < 2; ks++) {
#pragma unroll
            for (int nt = 0; nt < NTC; nt++) {
                uint4 q = Bs[(ks * NTC + nt) * 32 + lane];
                mma_f16acc(ccr[nt], al2[ks], q.x, q.y);   // lo_a * hi_b (f16 acc)
                mma_f16acc(ccr[nt], ah2[ks], q.z, q.w);   // hi_a * lo_b (f16 acc)
                mma_f16(chh[nt], ah2[ks], q.x, q.y);      // hi_a * hi_b (f32 acc)
            }
        }
    }

    const int rg = mt * 128 + r0;
#pragma unroll
    for (int nt = 0; nt < NTC; nt++) {
        int gc = NBASE + nt * 8 + t * 2;
        float bias0, bias1;
        float* Cout;
        int cc;
        if (gc < 196) { bias0 = bps[gc]; bias1 = bps[gc + 1]; Cout = Cps; cc = gc; }
        else { bias0 = bbb[gc - 196]; bias1 = bbb[gc - 195]; Cout = Cbb; cc = gc - 196; }
        __half2 q01 = *reinterpret_cast<__half2*>(&ccr[nt][0]);
        __half2 q23 = *reinterpret_cast<__half2*>(&ccr[nt][1]);
        float2 cr01 = __half22float2(q01);
        float2 cr23 = __half22float2(q23);
        float2 w0 = make_float2((chh[nt][0] + cr01.x) * INV_SCALE + bias0,
                                (chh[nt][1] + cr01.y) * INV_SCALE + bias1);
        float2 w1 = make_float2((chh[nt][2] + cr23.x) * INV_SCALE + bias0,
                                (chh[nt][3] + cr23.y) * INV_SCALE + bias1);
        *reinterpret_cast<float2*>(&Cout[(size_t)rg * 196 + cc]) = w0;
        *reinterpret_cast<float2*>(&Cout[(size_t)(rg + 8) * 196 + cc]) = w1;
    }
}

__global__ __launch_bounds__(256, 1) void gemm_mma(
    const float* __restrict__ A, const uint4* __restrict__ Bsp,
    const float* __restrict__ bps, const float* __restrict__ bbb,
    float* __restrict__ Cps, float* __restrict__ Cbb)
{
    extern __shared__ char smem[];
    int mt = blockIdx.x >> 1;
    if ((blockIdx.x & 1) == 0)
        gemm_body<25, 0, 0>(A, Bsp, bps, bbb, Cps, Cbb, smem, mt);
    else
        gemm_body<24, 200, 51200>(A, Bsp, bps, bbb, Cps, Cbb, smem, mt);
}

// ---------------- Bilinear PS-ROI sample ----------------
__device__ __forceinline__ void ps_sample4(const float* __restrict__ map,
                                           float y, float x, int cbase, float v[4])
{
    float y0f = floorf(y), x0f = floorf(x);
    float wy = y - y0f, wx = x - x0f;
    int y0 = (int)y0f; y0 = min(max(y0, 0), 159);
    int y1c = min(y0 + 1, 159);
    int x0 = (int)x0f; x0 = min(max(x0, 0), 159);
    int x1c = min(x0 + 1, 159);

    const float* p00 = map + (size_t)(y0 * 160 + x0) * 196 + cbase;
    const float* p01 = map + (size_t)(y0 * 160 + x1c) * 196 + cbase;
    const float* p10 = map + (size_t)(y1c * 160 + x0) * 196 + cbase;
    const float* p11 = map + (size_t)(y1c * 160 + x1c) * 196 + cbase;

    float w00 = (1.0f - wy) * (1.0f - wx);
    float w01 = (1.0f - wy) * wx;
    float w10 = wy * (1.0f - wx);
    float w11 = wy * wx;
#pragma unroll
    for (int p = 0; p < 4; p++) {
        v[p] = p00[p * 49] * w00 + p01[p * 49] * w01 +
               p10[p * 49] * w10 + p11[p * 49] * w11;
    }
}

__device__ __forceinline__ void roi_geom(const float* roi, int t,
                                         float& y, float& x, int& cb)
{
    float x1 = roi[1] * 0.125f;
    float yy1 = roi[2] * 0.125f;
    float x2 = roi[3] * 0.125f;
    float y2 = roi[4] * 0.125f;
    float bw = __fdiv_rn(x2 - x1, 7.0f);
    float bh = __fdiv_rn(y2 - yy1, 7.0f);
    int yI = t / 14, xI = t % 14;
    int i = yI >> 1, sy = yI & 1;
    int j = xI >> 1, sx = xI & 1;
    y = __fmaf_rn((float)i + (sy ? 0.75f : 0.25f), bh, yy1);
    x = __fmaf_rn((float)j + (sx ? 0.75f : 0.25f), bw, x1);
    cb = i * 7 + j;
}

// ---------------- fused: pooled4(rois 0..299) + proposal transform ----------------
__global__ __launch_bounds__(256) void pooled_prop_kernel(
    const float* __restrict__ rois,   // [300][5]
    const float* __restrict__ map,    // bb_map
    float* __restrict__ o_bb,         // [600][4] (rows 0..299)
    float* __restrict__ roisall,      // [600][5]
    float* __restrict__ out_roisall)  // d_out rois_all
{
    int r = blockIdx.x;
    const float* roi = rois + (size_t)r * 5;
    int t = threadIdx.x;
    float v[4] = {0.f, 0.f, 0.f, 0.f};
    if (t < 196) {
        float y, x; int cb;
        roi_geom(roi, t, y, x, cb);
        ps_sample4(map, y, x, cb, v);
    }

    __shared__ float red[4][256];
    __shared__ float s_off[4];
#pragma unroll
    for (int p = 0; p < 4; p++) red[p][t] = v[p];
    __syncthreads();
    for (int s = 128; s > 0; s >>= 1) {
        if (t < s) {
#pragma unroll
            for (int p = 0; p < 4; p++) red[p][t] += red[p][t + s];
        }
        __syncthreads();
    }
    if (t < 4) {
        float val = __fdiv_rn(red[t][0], 196.0f);
        o_bb[(size_t)r * 4 + t] = val;
        s_off[t] = val;
    }
    if (t < 5) {
        float val = roi[t];
        roisall[(size_t)r * 5 + t] = val;
        out_roisall[(size_t)r * 5 + t] = val;
    }
    __syncthreads();

    if (t == 0) {
        float x1 = roi[1], y1 = roi[2], x2 = roi[3], y2 = roi[4];
        float w = x2 - x1 + 1.0f, h = y2 - y1 + 1.0f;
        float cx = x1 + 0.5f * w, cy = y1 + 0.5f * h;
        float dx = s_off[0], dy = s_off[1], dw = s_off[2], dh = s_off[3];
        float pcx = dx * w + cx, pcy = dy * h + cy;
        float edw = (float)exp((double)dw);
        float edh = (float)exp((double)dh);
        float pw = edw * w, ph = edh * h;
        float px1 = pcx - 0.5f * pw, py1 = pcy - 0.5f * ph;
        float px2 = pcx + 0.5f * pw, py2 = pcy + 0.5f * ph;
        px1 = fminf(fmaxf(px1, 0.0f), 1279.0f);
        py1 = fminf(fmaxf(py1, 0.0f), 1279.0f);
        px2 = fminf(fmaxf(px2, 0.0f), 1279.0f);
        py2 = fminf(fmaxf(py2, 0.0f), 1279.0f);
        int rr = 300 + r;
        float vals[5] = {0.0f, px1, py1, px2, py2};
#pragma unroll
        for (int c = 0; c < 5; c++) {
            roisall[(size_t)rr * 5 + c] = vals[c];
            out_roisall[(size_t)rr * 5 + c] = vals[c];
        }
    }
}

// ---------------- roi_main: grid 900 ----------------------------------------------
__global__ __launch_bounds__(256) void roi_main_kernel(
    const float* __restrict__ roisall,
    const float* __restrict__ psmap,
    const float* __restrict__ bbmap,
    float* __restrict__ out_cls,
    float* __restrict__ out_res,
    float* __restrict__ out_score,
    float* __restrict__ out_mask,
    float* __restrict__ o_bb,
    float* __restrict__ scores)
{
    int b = blockIdx.x;
    int t = threadIdx.x;
    __shared__ float red[4][256];

    if (b >= 600) {
        int r = 300 + (b - 600);
        const float* roi = roisall + (size_t)r * 5;
        float vb[4] = {0.f, 0.f, 0.f, 0.f};
        if (t < 196) {
            float y, x; int cb;
            roi_geom(roi, t, y, x, cb);
            ps_sample4(bbmap, y, x, cb, vb);
        }
#pragma unroll
        for (int p = 0; p < 4; p++) red[p][t] = vb[p];
        __syncthreads();
        for (int s = 128; s > 0; s >>= 1) {
            if (t < s) {
#pragma unroll
                for (int p = 0; p < 4; p++) red[p][t] += red[p][t + s];
            }
            __syncthreads();
        }
        if (t < 4) o_bb[(size_t)r * 4 + t] = __fdiv_rn(red[t][0], 196.0f);
        return;
    }

    int r = b;
    const float* roi = roisall + (size_t)r * 5;
    float v[4] = {0.f, 0.f, 0.f, 0.f};
    float cm0 = 0.f, cm1 = 0.f;
    if (t < 196) {
        float y, x; int cb;
        roi_geom(roi, t, y, x, cb);
        ps_sample4(psmap, y, x, cb, v);
        cm0 = fmaxf(v[0], v[2]);
        cm1 = fmaxf(v[1], v[3]);
    }
    __shared__ int s_res;
    red[0][t] = cm0;
    red[1][t] = cm1;
    __syncthreads();
    for (int s = 128; s > 0; s >>= 1) {
        if (t < s) {
            red[0][t] += red[0][t + s];
            red[1][t] += red[1][t + s];
        }
        __syncthreads();
    }
    if (t == 0) {
        float a0 = __fdiv_rn(red[0][0], 196.0f);
        float a1 = __fdiv_rn(red[1][0], 196.0f);
        double m = (a0 > a1) ? (double)a0 : (double)a1;
        double e0 = exp((double)a0 - m);
        double e1 = exp((double)a1 - m);
        double inv = 1.0 / (e0 + e1);
        float c0 = (float)(e0 * inv);
        float c1 = (float)(e1 * inv);
        int res = (c1 > c0) ? 1 : 0;
        float sc = fmaxf(c0, c1);
        out_cls[(size_t)r * 2 + 0] = c0;
        out_cls[(size_t)r * 2 + 1] = c1;
        out_res[r] = (float)res;
        out_score[r] = sc;
        scores[r] = sc;
        s_res = res;
    }
    __syncthreads();

    if (t < 196) {
        int copy = s_res;
        float m0 = v[copy], m1 = v[2 + copy];
        float mm = fmaxf(m0, m1);
        float e0 = expf(m0 - mm);
        float e1 = expf(m1 - mm);
        float s = e0 + e1;
        out_mask[(size_t)r * 392 + t * 2 + 0] = __fdiv_rn(e0, s);
        out_mask[(size_t)r * 392 + t * 2 + 1] = __fdiv_rn(e1, s);
    }
}

// ---------------- NMS ----------------
__global__ __launch_bounds__(640) void nms_kernel(
    const float* __restrict__ roisall,
    const float* __restrict__ scores,
    float* __restrict__ out_keep)
{
    __shared__ float s_sc[600];
    __shared__ int s_ord[600];
    __shared__ float bxs[600 * 4];
    __shared__ float s_area[600];
    __shared__ unsigned char s_kept[600];

    int t = threadIdx.x;
    if (t < 600) s_sc[t] = scores[t];
    __syncthreads();

    if (t < 600) {
        float si = s_sc[t];
        int cnt = 0;
        for (int j = 0; j < 600; j++) {
            float sj = s_sc[j];
            cnt += (sj > si) || (sj == si && j < t);
        }
        s_ord[cnt] = t;
    }
    __syncthreads();

    float bx1 = 0.f, by1 = 0.f, bx2 = 0.f, by2 = 0.f, myArea = 0.f;
    bool kept_self = false;
    if (t < 600) {
        int o = s_ord[t];
        bx1 = roisall[(size_t)o * 5 + 1];
        by1 = roisall[(size_t)o * 5 + 2];
        bx2 = roisall[(size_t)o * 5 + 3];
        by2 = roisall[(size_t)o * 5 + 4];
        myArea = fmaxf(bx2 - bx1, 0.0f) * fmaxf(by2 - by1, 0.0f);
        bxs[t * 4 + 0] = bx1;
        bxs[t * 4 + 1] = by1;
        bxs[t * 4 + 2] = bx2;
        bxs[t * 4 + 3] = by2;
        s_area[t] = myArea;
    }
    __syncthreads();

    for (int i = 0; i < 600; i++) {
        bool p = false;
        if (t < i && kept_self) {
            float cx1 = bxs[i * 4 + 0], cy1 = bxs[i * 4 + 1];
            float cx2 = bxs[i * 4 + 2], cy2 = bxs[i * 4 + 3];
            float ix1 = fmaxf(cx1, bx1), iy1 = fmaxf(cy1, by1);
            float ix2 = fminf(cx2, bx2), iy2 = fminf(cy2, by2);
            float inter = fmaxf(ix2 - ix1, 0.0f) * fmaxf(iy2 - iy1, 0.0f);
            float denom = s_area[i] + myArea - inter + 1e-8f;
            float iou = __fdiv_rn(inter, denom);
            p = iou > 0.3f;
        }
        int any = __syncthreads_or((int)p);
        if (t == i) kept_self = !any;
    }

    if (t < 600) s_kept[t] = kept_self ? 1 : 0;
    __syncthreads();

    if (t == 0) {
        int rc = 0;
        for (int p2 = 0; p2 < 600 && rc < 300; p2++) {
            if (s_kept[p2]) out_keep[rc++] = (float)s_ord[p2];
        }
        for (; rc < 300; rc++) out_keep[rc] = -1.0f;
    }
}

// ---------------- launch ----------------
extern "C" void kernel_launch(void* const* d_in, const int* in_sizes, int n_in,
                              void* d_out, int out_size)
{
    const float* feat = (const float*)d_in[0];
    const float* Wps  = (const float*)d_in[1];
    const float* bps  = (const float*)d_in[2];
    const float* Wbb  = (const float*)d_in[3];
    const float* bbb  = (const float*)d_in[4];
    const float* rois = (const float*)d_in[5];

    float* out = (float*)d_out;
    float* o_cls  = out;
    float* o_res  = out + 1200;
    float* o_sc   = out + 1800;
    float* o_mask = out + 2400;
    float* o_ra   = out + 237600;
    float* o_bb   = out + 240600;
    float* o_keep = out + 243000;

    float *p_ps, *p_bb, *p_ra, *p_sc;
    uint4 *p_B;
    cudaGetSymbolAddress((void**)&p_ps, g_ps);
    cudaGetSymbolAddress((void**)&p_bb, g_bb);
    cudaGetSymbolAddress((void**)&p_ra, g_roisall);
    cudaGetSymbolAddress((void**)&p_sc, g_scores);
    cudaGetSymbolAddress((void**)&p_B, g_Bsp);

    cudaFuncSetAttribute(gemm_mma, cudaFuncAttributeMaxDynamicSharedMemorySize,
                         GEMM_SMEM);

    // 0. pre-split W (tiny)
    prep_B<<<392, 256>>>(Wps, Wbb, p_B);
    // 1. feature maps (fp32 A streamed, hoisted dual-ks split)
    gemm_mma<<<400, 256, GEMM_SMEM>>>(feat, p_B, bps, bbb, p_ps, p_bb);
    // 2. pooled offsets (== bbox[0:300]) + proposal transform, fused
    pooled_prop_kernel<<<300, 256>>>(rois, p_bb, o_bb, p_ra, o_ra);
    // 3. cls/score/mask (600 blocks) + bbox pooling for proposals (300 blocks)
    roi_main_kernel<<<900, 256>>>(p_ra, p_ps, p_bb, o_cls, o_res, o_sc,
                                  o_mask, o_bb, p_sc);
    // 4. NMS
    nms_kernel<<<1, 640>>>(p_ra, p_sc, o_keep);
}